// round 13
// baseline (speedup 1.0000x reference)
#include <cuda_runtime.h>
#include <cuda_bf16.h>

#define NB 16
#define NC 64
#define NH 128
#define NW 128
#define NE 8
#define NGH 16

__device__ float g_pooled[NB * NC];
__device__ float g_probs[NB][NE];
__device__ float g_bcomb[NB][NC];
// A in mma-fragment order: [b][tap][mtile(4)][kc(4)][lane(32)][j(4)] bf16x2 words
#define FRAG_WORDS (NB * 9 * 4 * 4 * 32 * 4)
__device__ unsigned g_wfrag_h[FRAG_WORDS];
__device__ unsigned g_wfrag_l[FRAG_WORDS];

__device__ __forceinline__ unsigned smem_u32(const void* p) {
    return (unsigned)__cvta_generic_to_shared(p);
}

#define LDSM_X4(r0, r1, r2, r3, addr) \
    asm volatile("ldmatrix.sync.aligned.m8n8.x4.shared.b16 {%0,%1,%2,%3}, [%4];" \
                 : "=r"(r0), "=r"(r1), "=r"(r2), "=r"(r3) : "r"(addr))

#define MMA_BF16(d, a0, a1, a2, a3, b0, b1) \
    asm volatile("mma.sync.aligned.m16n8k16.row.col.f32.bf16.bf16.f32 " \
                 "{%0,%1,%2,%3}, {%4,%5,%6,%7}, {%8,%9}, {%0,%1,%2,%3};" \
                 : "+f"(d[0]), "+f"(d[1]), "+f"(d[2]), "+f"(d[3]) \
                 : "r"(a0), "r"(a1), "r"(a2), "r"(a3), "r"(b0), "r"(b1))

// ---------------------------------------------------------------------------
// Kernel 1a: parallel GAP. One block per (b, c).
// ---------------------------------------------------------------------------
__global__ __launch_bounds__(256)
void pool_kernel(const float* __restrict__ x) {
    const int bc = blockIdx.x;
    const int tid = threadIdx.x;
    const float4* p4 = (const float4*)(x + (size_t)bc * NH * NW);

    float s = 0.f;
    #pragma unroll 4
    for (int i = tid; i < (NH * NW) / 4; i += 256) {
        float4 v = p4[i];
        s += (v.x + v.y) + (v.z + v.w);
    }
    #pragma unroll
    for (int o = 16; o > 0; o >>= 1) s += __shfl_xor_sync(0xffffffffu, s, o);

    __shared__ float ws[8];
    if ((tid & 31) == 0) ws[tid >> 5] = s;
    __syncthreads();
    if (tid == 0) {
        float t = 0.f;
        #pragma unroll
        for (int w = 0; w < 8; w++) t += ws[w];
        g_pooled[bc] = t * (1.0f / (NH * NW));
    }
}

// ---------------------------------------------------------------------------
// Kernel 1b: gating MLP + softmax + top-2.
// ---------------------------------------------------------------------------
__global__ void gate_kernel(const float* __restrict__ wg1,
                            const float* __restrict__ bg1,
                            const float* __restrict__ wg2,
                            const float* __restrict__ bg2) {
    const int b = blockIdx.x;
    const int tid = threadIdx.x;  // 64 threads

    __shared__ float pooled[NC];
    __shared__ float hbuf[NGH];
    __shared__ float logits[NE];

    if (tid < NC) pooled[tid] = g_pooled[b * NC + tid];
    __syncthreads();

    if (tid < NGH) {
        float a = bg1[tid];
        #pragma unroll
        for (int c = 0; c < NC; c++) a += pooled[c] * wg1[c * NGH + tid];
        hbuf[tid] = a > 0.f ? a : 0.f;
    }
    __syncthreads();

    if (tid < NE) {
        float a = bg2[tid];
        #pragma unroll
        for (int g = 0; g < NGH; g++) a += hbuf[g] * wg2[g * NE + tid];
        logits[tid] = a;
    }
    __syncthreads();

    if (tid == 0) {
        float m = -1e30f;
        #pragma unroll
        for (int e = 0; e < NE; e++) m = fmaxf(m, logits[e]);
        float p[NE], s = 0.f;
        #pragma unroll
        for (int e = 0; e < NE; e++) { p[e] = expf(logits[e] - m); s += p[e]; }
        float inv = 1.0f / s;
        #pragma unroll
        for (int e = 0; e < NE; e++) p[e] *= inv;
        int i1 = 0;
        #pragma unroll
        for (int e = 1; e < NE; e++) if (p[e] > p[i1]) i1 = e;
        int i2 = -1;
        #pragma unroll
        for (int e = 0; e < NE; e++) {
            if (e == i1) continue;
            if (i2 < 0 || p[e] > p[i2]) i2 = e;
        }
        float denom = p[i1] + p[i2] + 1e-8f;
        #pragma unroll
        for (int e = 0; e < NE; e++)
            g_probs[b][e] = (e == i1 || e == i2) ? p[e] / denom : 0.f;
    }
}

// ---------------------------------------------------------------------------
// Kernel 2: fold routing probs into per-batch weights, split bf16 hi/lo,
// written directly in mma A-fragment order.
// For m16n8k16 row-major A: lane provides a_j with
//   row = mt*16 + (lane>>2) + (j&1)*8, col = kc*16 + (j>>1)*8 + (lane&3)*2 + h
// Inverse: mt=co>>4; r=co&15: r8=r>>3, lrow=r&7. kc=ci>>4; c=ci&15:
//   kh=c>>3, lcol=(c&7)>>1, h=c&1. lane=(lrow<<2)|lcol. j=(kh<<1)|r8.
// ---------------------------------------------------------------------------
__global__ void combine_kernel(const float* __restrict__ w_exp,
                               const float* __restrict__ b_exp) {
    const int idx = blockIdx.x * blockDim.x + threadIdx.x;
    const int total = NB * 9 * NC * NC;
    if (idx < total) {
        const int b   = idx / (9 * NC * NC);
        const int r0  = idx - b * (9 * NC * NC);
        const int tap = r0 / (NC * NC);
        const int r1  = r0 - tap * (NC * NC);
        const int co  = r1 / NC;
        const int ci  = r1 - co * NC;
        float s = 0.f;
        #pragma unroll
        for (int e = 0; e < NE; e++)
            s += g_probs[b][e] * w_exp[((size_t)(e * NC + co) * NC + ci) * 9 + tap];
        const __nv_bfloat16 hi = __float2bfloat16(s);
        const __nv_bfloat16 lo = __float2bfloat16(s - __bfloat162float(hi));

        const int mt = co >> 4, r = co & 15;
        const int kc = ci >> 4, c = ci & 15;
        const int lane = ((r & 7) << 2) | ((c & 7) >> 1);
        const int j    = ((c >> 3) << 1) | (r >> 3);
        const int word = ((((b * 9 + tap) * 4 + mt) * 4 + kc) * 32 + lane) * 4 + j;
        ((__nv_bfloat16*)g_wfrag_h)[word * 2 + (c & 1)] = hi;
        ((__nv_bfloat16*)g_wfrag_l)[word * 2 + (c & 1)] = lo;
    }
    if (idx < NB * NC) {
        const int b = idx / NC, c = idx - b * NC;
        float s = 0.f;
        #pragma unroll
        for (int e = 0; e < NE; e++) s += g_probs[b][e] * b_exp[e * NC + c];
        g_bcomb[b][c] = s;
    }
}

// ---------------------------------------------------------------------------
// Kernel 3: implicit-GEMM conv, barrier-free tap loop.
// CTA: 16(h) x 8(w) pixels of one batch. 8 warps, each m64 x n16
// (all 4 co-tiles x 2 n8 frags; warp nw covers pixel rows nw*2, nw*2+1).
// B (input, hi/lo split, swizzled) staged once in smem; A fragments
// LDG.128'd from gmem (L1-broadcast across warps/CTAs). 3-pass split bf16.
// ---------------------------------------------------------------------------
#define TPY 16
#define TPX 8
#define PRW (TPX + 2)                    // 10
#define PROWS ((TPY + 2) * PRW)          // 180
#define SMEM_BYTES (PROWS * NC * 2 * 2)  // 46080

__global__ __launch_bounds__(256)
void conv_mma_kernel(const float* __restrict__ x, float* __restrict__ out) {
    const int b  = blockIdx.z;
    const int X0 = blockIdx.x * TPX;
    const int Y0 = blockIdx.y * TPY;

    extern __shared__ __align__(16) char smem_raw[];
    __nv_bfloat16* Bh = (__nv_bfloat16*)smem_raw;   // [180][64] swizzled
    __nv_bfloat16* Bl = Bh + PROWS * NC;

    const int tid  = threadIdx.x;
    const int lane = tid & 31;
    const int nw   = tid >> 5;   // warp = pixel-row pair

    // ---- stage input tile (hi/lo split, swizzled), once ----
    const float* xb = x + (size_t)b * NC * NH * NW;
    for (int i = tid; i < PROWS * NC; i += 256) {
        const int ci = i / PROWS;
        const int r  = i - ci * PROWS;
        const int ly = r / PRW, lx = r - ly * PRW;
        const int gy = Y0 - 1 + ly, gx = X0 - 1 + lx;
        float v = 0.f;
        if (gy >= 0 && gy < NH && gx >= 0 && gx < NW)
            v = xb[ci * (NH * NW) + gy * NW + gx];
        const __nv_bfloat16 hi = __float2bfloat16(v);
        const __nv_bfloat16 lo = __float2bfloat16(v - __bfloat162float(hi));
        const int off = r * NC + ((((ci >> 3) ^ (r & 7)) << 3) | (ci & 7));
        Bh[off] = hi;
        Bl[off] = lo;
    }
    __syncthreads();   // the only barrier

    const unsigned BhB = smem_u32(Bh), BlB = smem_u32(Bl);

    // B ldmatrix x4 lane roles: f = lane>>4, khalf = (lane>>3)&1, jx = lane&7
    const int bf    = lane >> 4;
    const int bkh   = (lane >> 3) & 1;
    const int bjx   = lane & 7;

    float acc[4][2][4];
    #pragma unroll
    for (int mt = 0; mt < 4; mt++)
        #pragma unroll
        for (int f = 0; f < 2; f++)
            #pragma unroll
            for (int q = 0; q < 4; q++) acc[mt][f][q] = 0.f;

    const uint4* Ah4 = (const uint4*)g_wfrag_h;
    const uint4* Al4 = (const uint4*)g_wfrag_l;

    for (int tap = 0; tap < 9; tap++) {
        const int ky = tap / 3, kx = tap - ky * 3;
        // B-tile row for this lane's (pixel y = nw*2 + f, x = jx) at this tap
        const int row = (nw * 2 + bf + ky) * PRW + bjx + kx;
        const int rowbase = row << 7;   // *128 bytes
        const int sw = row & 7;
        // A fragment base for this tap: [tap][mt][kc] blocks of 32 uint4
        const size_t abase = ((size_t)(b * 9 + tap) * 16) * 32 + lane;

        #pragma unroll
        for (int kc = 0; kc < 4; kc++) {
            const unsigned bu =
                (unsigned)(rowbase + ((((kc << 1) | bkh) ^ sw) << 4));
            unsigned bh0, bh1, bh2, bh3, bl0, bl1, bl2, bl3;
            LDSM_X4(bh0, bh1, bh2, bh3, BhB + bu);
            LDSM_X4(bl0, bl1, bl2, bl3, BlB + bu);

            uint4 ah[4], al[4];
            #pragma unroll
            for (int mt = 0; mt < 4; mt++) {
                const size_t ai = abase + (size_t)(mt * 4 + kc) * 32;
                ah[mt] = Ah4[ai];
                al[mt] = Al4[ai];
            }

            #pragma unroll
            for (int mt = 0; mt < 4; mt++) {
                MMA_BF16(acc[mt][0], ah[mt].x, ah[mt].y, ah[mt].z, ah[mt].w, bh0, bh1);
                MMA_BF16(acc[mt][1], ah[mt].x, ah[mt].y, ah[mt].z, ah[mt].w, bh2, bh3);
                MMA_BF16(acc[mt][0], ah[mt].x, ah[mt].y, ah[mt].z, ah[mt].w, bl0, bl1);
                MMA_BF16(acc[mt][1], ah[mt].x, ah[mt].y, ah[mt].z, ah[mt].w, bl2, bl3);
                MMA_BF16(acc[mt][0], al[mt].x, al[mt].y, al[mt].z, al[mt].w, bh0, bh1);
                MMA_BF16(acc[mt][1], al[mt].x, al[mt].y, al[mt].z, al[mt].w, bh2, bh3);
            }
        }
    }

    // ---- epilogue: bias + residual ----
    // acc quad q: co = mt*16 + (lane>>2) + (q>>1)*8,
    //             pixel n = nw*16 + f*8 + (lane&3)*2 + (q&1)
    #pragma unroll
    for (int mt = 0; mt < 4; mt++) {
        #pragma unroll
        for (int f = 0; f < 2; f++) {
            const int n  = nw * 16 + f * 8 + ((lane & 3) << 1);
            const int gy = Y0 + (n >> 3);
            const int gx = X0 + (n & 7);
            #pragma unroll
            for (int h = 0; h < 2; h++) {
                const int co = mt * 16 + (lane >> 2) + h * 8;
                const float bias = g_bcomb[b][co];
                const size_t o = ((size_t)(b * NC + co) * NH + gy) * NW + gx;
                const float2 res = *(const float2*)(x + o);
                float2 v;
                v.x = acc[mt][f][h * 2 + 0] + bias + res.x;
                v.y = acc[mt][f][h * 2 + 1] + bias + res.y;
                *(float2*)(out + o) = v;
            }
        }
    }
}

extern "C" void kernel_launch(void* const* d_in, const int* in_sizes, int n_in,
                              void* d_out, int out_size) {
    const float* x     = (const float*)d_in[0];
    const float* wg1   = (const float*)d_in[1];
    const float* bg1   = (const float*)d_in[2];
    const float* wg2   = (const float*)d_in[3];
    const float* bg2   = (const float*)d_in[4];
    const float* w_exp = (const float*)d_in[5];
    const float* b_exp = (const float*)d_in[6];
    float* out = (float*)d_out;

    pool_kernel<<<NB * NC, 256>>>(x);
    gate_kernel<<<NB, 64>>>(wg1, bg1, wg2, bg2);

    const int total = NB * 9 * NC * NC;
    combine_kernel<<<(total + 255) / 256, 256>>>(w_exp, b_exp);

    dim3 grid(NW / TPX, NH / TPY, NB);   // (16, 8, 16)
    conv_mma_kernel<<<grid, 256, SMEM_BYTES>>>(x, out);
}